// round 15
// baseline (speedup 1.0000x reference)
#include <cuda_runtime.h>
#include <cuda_fp16.h>
#include <math.h>
#include <stdint.h>

// Problem constants
#define BATCH   2
#define SEQ     2048
#define DMODEL  2048
#define NH      32
#define NKV     8
#define HD      64
#define QPOS    (NH * HD)            // 2048
#define KVPOS   (NKV * HD)           // 512
#define OPS     (QPOS + 2 * KVPOS)   // 3072
#define MTOT    (BATCH * SEQ)        // 4096
// q is pre-scaled by ATTN_SCALE * log2(e); softmax runs in base-2 domain
#define QSCALE  (0.125f * 1.4426950408889634f)

// ---------------------------------------------------------------------------
// Scratch (device globals) — fp16 operands everywhere, fp32 accumulate
// ---------------------------------------------------------------------------
__device__ __half g_x [MTOT * DMODEL];
__device__ __half g_wq[OPS * DMODEL];
__device__ __half g_wo[DMODEL * DMODEL];
// per-head-contiguous roped q/k and v: [b][h][seq][64]
__device__ __half g_qh[BATCH * NH  * SEQ * HD];
__device__ __half g_kh[BATCH * NKV * SEQ * HD];
__device__ __half g_vh[BATCH * NKV * SEQ * HD];
// attention output [row][2048] (O-proj A operand)
__device__ __half g_ah[MTOT * QPOS];
__device__ float2 g_rope[SEQ * 32];

// ---------------------------------------------------------------------------
// helpers
// ---------------------------------------------------------------------------
__device__ __forceinline__ uint32_t smem_to_u32(const void* p) {
    uint32_t a;
    asm("{ .reg .u64 t; cvta.to.shared.u64 t, %1; cvt.u32.u64 %0, t; }"
        : "=r"(a) : "l"(p));
    return a;
}

__device__ __forceinline__ void cp_async16(uint32_t smem_dst, const void* gmem_src) {
    asm volatile("cp.async.cg.shared.global [%0], [%1], 16;"
                 :: "r"(smem_dst), "l"(gmem_src) : "memory");
}
__device__ __forceinline__ void cp_commit() {
    asm volatile("cp.async.commit_group;" ::: "memory");
}
__device__ __forceinline__ void cp_wait0() {
    asm volatile("cp.async.wait_group 0;" ::: "memory");
}
__device__ __forceinline__ void cp_wait1() {
    asm volatile("cp.async.wait_group 1;" ::: "memory");
}

__device__ __forceinline__ void ldsm_x4(uint32_t& r0, uint32_t& r1,
                                        uint32_t& r2, uint32_t& r3, uint32_t addr) {
    asm volatile("ldmatrix.sync.aligned.m8n8.x4.shared.b16 {%0,%1,%2,%3}, [%4];"
                 : "=r"(r0), "=r"(r1), "=r"(r2), "=r"(r3) : "r"(addr));
}
__device__ __forceinline__ void ldsm_x4_trans(uint32_t& r0, uint32_t& r1,
                                              uint32_t& r2, uint32_t& r3, uint32_t addr) {
    asm volatile("ldmatrix.sync.aligned.m8n8.x4.trans.shared.b16 {%0,%1,%2,%3}, [%4];"
                 : "=r"(r0), "=r"(r1), "=r"(r2), "=r"(r3) : "r"(addr));
}

// fp16 mma m16n8k16, fp32 accumulate
__device__ __forceinline__ void mma_f16(float& d0, float& d1, float& d2, float& d3,
                                        uint32_t a0, uint32_t a1, uint32_t a2, uint32_t a3,
                                        uint32_t b0, uint32_t b1) {
    asm volatile(
        "mma.sync.aligned.m16n8k16.row.col.f32.f16.f16.f32 "
        "{%0,%1,%2,%3}, {%4,%5,%6,%7}, {%8,%9}, {%0,%1,%2,%3};"
        : "+f"(d0), "+f"(d1), "+f"(d2), "+f"(d3)
        : "r"(a0), "r"(a1), "r"(a2), "r"(a3), "r"(b0), "r"(b1));
}

__device__ __forceinline__ uint32_t pack_h2(float x, float y) {
    __half2 t = __floats2half2_rn(x, y);
    return *(uint32_t*)&t;
}

__device__ __forceinline__ float ex2f(float x) {
    float y;
    asm("ex2.approx.f32 %0, %1;" : "=f"(y) : "f"(x));
    return y;
}

// ---------------------------------------------------------------------------
// Fused conversion: x, Wqkv, Wo -> fp16 in one launch (segment select)
// ---------------------------------------------------------------------------
#define N4_X  ((MTOT * DMODEL) / 4)
#define N4_WQ ((OPS * DMODEL) / 4)
#define N4_WO ((DMODEL * DMODEL) / 4)
#define N4_ALL (N4_X + N4_WQ + N4_WO)

__global__ void to_half_all_kernel(const float* __restrict__ x,
                                   const float* __restrict__ wq,
                                   const float* __restrict__ wo)
{
    int i = blockIdx.x * blockDim.x + threadIdx.x;
    if (i >= N4_ALL) return;
    const float* src;
    __half* dst;
    int j = i;
    if (j < N4_X) {
        src = x;  dst = g_x;
    } else if ((j -= N4_X) < N4_WQ) {
        src = wq; dst = g_wq;
    } else {
        j -= N4_WQ;
        src = wo; dst = g_wo;
    }
    float4 v = ((const float4*)src)[j];
    uint32_t* dp = (uint32_t*)dst;
    dp[2 * j]     = pack_h2(v.x, v.y);
    dp[2 * j + 1] = pack_h2(v.z, v.w);
}

__global__ void rope_table_kernel()
{
    int idx = blockIdx.x * blockDim.x + threadIdx.x;
    if (idx >= SEQ * 32) return;
    int l = idx >> 5, i = idx & 31;
    float ang = (float)l * powf(10000.0f, -(float)(2 * i) / (float)HD);
    float s, c;
    sincosf(ang, &s, &c);
    g_rope[idx] = make_float2(c, s);
}

// ---------------------------------------------------------------------------
// Single-pass fp16 GEMM: C[M,N] = A[M,K] * B[N,K]^T, fp32 accumulate.
// CTA tile 128x128, K-chunk 32, THREE-stage cp.async pipeline (wait_group 1).
// 4 warps (2m x 2n), warp tile 64x64. 3 CTAs/SM.
// MODE 0: fp32 C (O-projection).
// MODE 1: QKV epilogue — RoPE, fp16-round, per-head scatter.
//         q heads additionally scaled by QSCALE (softmax base-2 + attn scale).
// ---------------------------------------------------------------------------
#define LDSE  40                         // halves per smem row (80 B, conflict-free)
#define LDSB  (LDSE * 2)
#define TILE_B (128 * LDSB)              // 10240 B per operand
#define STAGE_B (2 * TILE_B)             // 20480 B per stage
#define NSTAGE 3
#define GEMM_SMEM (NSTAGE * STAGE_B)     // 61440 B; x3 CTAs = 184 KB

template <int MODE>
__global__ void __launch_bounds__(128, 3)
gemm_f16_kernel(const __half* __restrict__ A, const __half* __restrict__ B,
                float* __restrict__ C, int N, int K)
{
    extern __shared__ char smem[];
    const uint32_t sb = smem_to_u32(smem);

    const int tid  = threadIdx.x;
    const int lane = tid & 31;
    const int wid  = tid >> 5;
    const int wm   = wid >> 1;           // 0..1
    const int wn   = wid & 1;            // 0..1
    const int bm   = blockIdx.y * 128;
    const int bn   = blockIdx.x * 128;

    const __half* Ag = A + (size_t)bm * K;
    const __half* Bg = B + (size_t)bn * K;

    const int r0 = tid >> 2;             // rows 0..31 (+32*i)
    const int c0 = tid & 3;

    float acc[4][8][4];
#pragma unroll
    for (int i = 0; i < 4; i++)
#pragma unroll
        for (int j = 0; j < 8; j++)
#pragma unroll
            for (int t = 0; t < 4; t++) acc[i][j][t] = 0.f;

    const int iters = K / 32;

    const uint32_t a_ld_off =
        (uint32_t)((wm * 64 + (lane & 15)) * LDSB + (lane >> 4) * 16);
    const uint32_t b_ld_off =
        (uint32_t)((wn * 64 + (lane & 7) + ((lane >> 4) << 3)) * LDSB
                   + ((lane >> 3) & 1) * 16);

    auto load_stage = [&](int stage, int k0) {
        uint32_t base = sb + stage * STAGE_B;
#pragma unroll
        for (int i = 0; i < 4; i++) {
            int row = r0 + i * 32;
            uint32_t sofs = (uint32_t)(row * LDSB + c0 * 16);
            size_t gofs   = (size_t)row * K + k0 + c0 * 8;
            cp_async16(base + sofs,          Ag + gofs);
            cp_async16(base + TILE_B + sofs, Bg + gofs);
        }
        cp_commit();
    };

    load_stage(0, 0);
    load_stage(1, 32);

    for (int it = 0; it < iters; ++it) {
        if (it + 1 < iters) cp_wait1(); else cp_wait0();
        __syncthreads();
        if (it + 2 < iters) load_stage((it + 2) % NSTAGE, (it + 2) * 32);

        const uint32_t base = sb + (it % NSTAGE) * STAGE_B;
        const uint32_t sA = base + a_ld_off;
        const uint32_t sB = base + TILE_B + b_ld_off;

#pragma unroll
        for (int ks = 0; ks < 2; ks++) {
            const uint32_t kofs = ks * 32;       // 16 halves = 32 B
            uint32_t af[4][4];
#pragma unroll
            for (int mt = 0; mt < 4; mt++)
                ldsm_x4(af[mt][0], af[mt][1], af[mt][2], af[mt][3],
                        sA + mt * 16 * LDSB + kofs);
#pragma unroll
            for (int np = 0; np < 4; np++) {
                uint32_t bf[4];
                ldsm_x4(bf[0], bf[1], bf[2], bf[3], sB + np * 16 * LDSB + kofs);
                const int j0 = 2 * np, j1 = 2 * np + 1;
#pragma unroll
                for (int mt = 0; mt < 4; mt++) {
                    mma_f16(acc[mt][j0][0], acc[mt][j0][1], acc[mt][j0][2], acc[mt][j0][3],
                            af[mt][0], af[mt][1], af[mt][2], af[mt][3], bf[0], bf[1]);
                    mma_f16(acc[mt][j1][0], acc[mt][j1][1], acc[mt][j1][2], acc[mt][j1][3],
                            af[mt][0], af[mt][1], af[mt][2], af[mt][3], bf[2], bf[3]);
                }
            }
        }
    }

    const int c2v = (lane & 3) * 2;

    if (MODE == 0) {
#pragma unroll
        for (int mt = 0; mt < 4; mt++) {
            int row = bm + wm * 64 + mt * 16 + (lane >> 2);
#pragma unroll
            for (int nt = 0; nt < 8; nt++) {
                int col = bn + wn * 64 + nt * 8 + c2v;
                *(float2*)&C[(size_t)row * N + col] =
                    make_float2(acc[mt][nt][0], acc[mt][nt][1]);
                *(float2*)&C[(size_t)(row + 8) * N + col] =
                    make_float2(acc[mt][nt][2], acc[mt][nt][3]);
            }
        }
    } else {
        // QKV epilogue: rope + fp16-round + per-head scatter (warp panel = 1 head)
        const int head = (bn + wn * 64) >> 6;   // 0..47
#pragma unroll
        for (int mt = 0; mt < 4; mt++) {
            int grow = bm + wm * 64 + mt * 16 + (lane >> 2);
            int b = grow >> 11;
            int l = grow & (SEQ - 1);
            __half* dh;
            bool rope;
            float sc = 1.f;
            if (head < NH) {
                dh = g_qh + ((size_t)(b * NH + head) * SEQ + l) * HD;
                rope = true;
                sc = QSCALE;                      // pre-scale q for base-2 softmax
            } else if (head < NH + NKV) {
                dh = g_kh + ((size_t)(b * NKV + (head - NH)) * SEQ + l) * HD;
                rope = true;
            } else {
                dh = g_vh + ((size_t)(b * NKV + (head - NH - NKV)) * SEQ + l) * HD;
                rope = false;
            }
#pragma unroll
            for (int nt = 0; nt < 4; nt++) {
                int i0 = nt * 8 + c2v;
                float x0 = acc[mt][nt][0],     x1 = acc[mt][nt][1];
                float y0 = acc[mt][nt + 4][0], y1 = acc[mt][nt + 4][1];
                float x2 = acc[mt][nt][2],     x3 = acc[mt][nt][3];
                float y2 = acc[mt][nt + 4][2], y3 = acc[mt][nt + 4][3];
                if (rope) {
                    float2 cs0 = g_rope[l * 32 + i0];
                    float2 cs1 = g_rope[l * 32 + i0 + 1];
                    float2 cs2 = g_rope[(l + 8) * 32 + i0];
                    float2 cs3 = g_rope[(l + 8) * 32 + i0 + 1];
                    float nx;
                    nx = x0 * cs0.x - y0 * cs0.y; y0 = y0 * cs0.x + x0 * cs0.y; x0 = nx;
                    nx = x1 * cs1.x - y1 * cs1.y; y1 = y1 * cs1.x + x1 * cs1.y; x1 = nx;
                    nx = x2 * cs2.x - y2 * cs2.y; y2 = y2 * cs2.x + x2 * cs2.y; x2 = nx;
                    nx = x3 * cs3.x - y3 * cs3.y; y3 = y3 * cs3.x + x3 * cs3.y; x3 = nx;
                }
                *(uint32_t*)(dh + i0)               = pack_h2(x0 * sc, x1 * sc);
                *(uint32_t*)(dh + i0 + 32)          = pack_h2(y0 * sc, y1 * sc);
                *(uint32_t*)(dh + 8 * HD + i0)      = pack_h2(x2 * sc, x3 * sc);
                *(uint32_t*)(dh + 8 * HD + i0 + 32) = pack_h2(y2 * sc, y3 * sc);
            }
        }
    }
}

// ---------------------------------------------------------------------------
// Flash attention, single-pass fp16 mma, base-2 softmax (q pre-scaled).
// CTA: 64 q-rows, 4 warps. KV tiles of 64 keys, double-buffered, 3 CTAs/SM.
// ---------------------------------------------------------------------------
#define A_LDSB  144                      // 72 halves per row
#define A_TILE  (64 * A_LDSB)            // 9216 B
#define A_STAGE (2 * A_TILE)             // K + V = 18432 B
#define ATTN_SMEM (2 * A_STAGE)          // 36864 B; x3 CTAs = 110 KB
#define AT_KH 0
#define AT_VH A_TILE

__global__ void __launch_bounds__(128, 3)
attn_f16_kernel()
{
    extern __shared__ char smem[];
    const uint32_t sb = smem_to_u32(smem);

    const int tid  = threadIdx.x;
    const int lane = tid & 31;
    const int wid  = tid >> 5;
    const int bx   = (int)gridDim.x - 1 - (int)blockIdx.x;   // heavy first
    const int q0   = bx * 64;
    const int hq   = blockIdx.y;
    const int b    = blockIdx.z;
    const int kvh  = hq >> 2;
    const int r    = lane >> 2;
    const int c2   = (lane & 3) * 2;

    const size_t qoff = ((size_t)(b * NH + hq) * SEQ + q0 + wid * 16 + r) * HD;
    const __half* qh0 = g_qh + qoff;
    const __half* qh1 = qh0 + 8 * HD;
    uint32_t qf[4][4];
#pragma unroll
    for (int ks = 0; ks < 4; ks++) {
        qf[ks][0] = *(const uint32_t*)(qh0 + ks * 16 + c2);
        qf[ks][1] = *(const uint32_t*)(qh1 + ks * 16 + c2);
        qf[ks][2] = *(const uint32_t*)(qh0 + ks * 16 + c2 + 8);
        qf[ks][3] = *(const uint32_t*)(qh1 + ks * 16 + c2 + 8);
    }

    const __half* kg = g_kh + (size_t)(b * NKV + kvh) * SEQ * HD;
    const __half* vg = g_vh + (size_t)(b * NKV + kvh) * SEQ * HD;

    auto load_stage = [&](int st, int kt) {
        uint32_t base = sb + st * A_STAGE;
#pragma unroll
        for (int i = 0; i < 4; i++) {
            int lin = tid + i * 128;
            int row = lin >> 3;
            int c   = lin & 7;
            uint32_t sofs = (uint32_t)(row * A_LDSB + c * 16);
            size_t gofs   = (size_t)(kt + row) * HD + c * 8;
            cp_async16(base + AT_KH + sofs, kg + gofs);
            cp_async16(base + AT_VH + sofs, vg + gofs);
        }
        cp_commit();
    };

    const int iters = bx + 1;
    load_stage(0, 0);

    float o[8][4];
#pragma unroll
    for (int j = 0; j < 8; j++)
#pragma unroll
        for (int t = 0; t < 4; t++) o[j][t] = 0.f;
    float m0 = -1e30f, m1 = -1e30f, l0 = 0.f, l1 = 0.f;

    const uint32_t kcore = (uint32_t)(((lane & 7) + ((lane >> 4) << 3)) * A_LDSB
                                      + ((lane >> 3) & 1) * 16);
    const uint32_t vcore = (uint32_t)((lane & 15) * A_LDSB + ((lane >> 4) << 4));

    for (int it = 0; it < iters; ++it) {
        const int kt = it * 64;
        cp_wait0();
        __syncthreads();
        if (it + 1 < iters) load_stage((it + 1) & 1, (it + 1) * 64);

        const uint32_t base = sb + (it & 1) * A_STAGE;

        // ---- S = Q K^T (q pre-scaled; scores already in log2 domain)
        float s[8][4];
#pragma unroll
        for (int j = 0; j < 8; j++)
#pragma unroll
            for (int t = 0; t < 4; t++) s[j][t] = 0.f;

#pragma unroll
        for (int kk = 0; kk < 4; kk++) {
#pragma unroll
            for (int np = 0; np < 4; np++) {
                uint32_t kb[4];
                ldsm_x4(kb[0], kb[1], kb[2], kb[3],
                        base + AT_KH + kcore + np * 16 * A_LDSB + kk * 32);
                int j0 = 2 * np, j1 = 2 * np + 1;
                mma_f16(s[j0][0], s[j0][1], s[j0][2], s[j0][3],
                        qf[kk][0], qf[kk][1], qf[kk][2], qf[kk][3], kb[0], kb[1]);
                mma_f16(s[j1][0], s[j1][1], s[j1][2], s[j1][3],
                        qf[kk][0], qf[kk][1], qf[kk][2], qf[kk][3], kb[2], kb[3]);
            }
        }

        if (kt == q0) {
            int row0 = q0 + wid * 16 + r;
#pragma unroll
            for (int j = 0; j < 8; j++) {
                int col = kt + j * 8 + c2;
                if (col > row0)     s[j][0] = -1e30f;
                if (col + 1 > row0) s[j][1] = -1e30f;
                if (col > row0 + 8)     s[j][2] = -1e30f;
                if (col + 1 > row0 + 8) s[j][3] = -1e30f;
            }
        }

        // ---- online softmax (base 2)
        float mx0 = -1e30f, mx1 = -1e30f;
#pragma unroll
        for (int j = 0; j < 8; j++) {
            mx0 = fmaxf(mx0, fmaxf(s[j][0], s[j][1]));
            mx1 = fmaxf(mx1, fmaxf(s[j][2], s[j][3]));
        }
        mx0 = fmaxf(mx0, __shfl_xor_sync(0xffffffffu, mx0, 1));
        mx0 = fmaxf(mx0, __shfl_xor_sync(0xffffffffu, mx0, 2));
        mx1 = fmaxf(mx1, __shfl_xor_sync(0xffffffffu, mx1, 1));
        mx1 = fmaxf(mx1, __shfl_xor_sync(0xffffffffu, mx1, 2));

        if (mx0 > m0) {
            float corr0 = ex2f(m0 - mx0);
            l0 *= corr0;
#pragma unroll
            for (int j = 0; j < 8; j++) { o[j][0] *= corr0; o[j][1] *= corr0; }
            m0 = mx0;
        }
        if (mx1 > m1) {
            float corr1 = ex2f(m1 - mx1);
            l1 *= corr1;
#pragma unroll
            for (int j = 0; j < 8; j++) { o[j][2] *= corr1; o[j][3] *= corr1; }
            m1 = mx1;
        }

#pragma unroll
        for (int j = 0; j < 8; j++) {
            float p0 = ex2f(s[j][0] - m0);
            float p1 = ex2f(s[j][1] - m0);
            float p2 = ex2f(s[j][2] - m1);
            float p3 = ex2f(s[j][3] - m1);
            l0 += p0 + p1; l1 += p2 + p3;
            s[j][0] = p0; s[j][1] = p1; s[j][2] = p2; s[j][3] = p3;
        }

        // ---- O += P V (fp16). P A-fragments from S registers (FA2 identity)
#pragma unroll
        for (int kk = 0; kk < 4; kk++) {
            uint32_t pa[4];
            pa[0] = pack_h2(s[2*kk][0],   s[2*kk][1]);
            pa[1] = pack_h2(s[2*kk][2],   s[2*kk][3]);
            pa[2] = pack_h2(s[2*kk+1][0], s[2*kk+1][1]);
            pa[3] = pack_h2(s[2*kk+1][2], s[2*kk+1][3]);
#pragma unroll
            for (int np = 0; np < 4; np++) {
                uint32_t vb[4];
                ldsm_x4_trans(vb[0], vb[1], vb[2], vb[3],
                              base + AT_VH + vcore + kk * 16 * A_LDSB + np * 32);
                int j0 = 2 * np, j1 = 2 * np + 1;
                mma_f16(o[j0][0], o[j0][1], o[j0][2], o[j0][3],
                        pa[0], pa[1], pa[2], pa[3], vb[0], vb[1]);
                mma_f16(o[j1][0], o[j1][1], o[j1][2], o[j1][3],
                        pa[0], pa[1], pa[2], pa[3], vb[2], vb[3]);
            }
        }
    }

    l0 += __shfl_xor_sync(0xffffffffu, l0, 1);
    l0 += __shfl_xor_sync(0xffffffffu, l0, 2);
    l1 += __shfl_xor_sync(0xffffffffu, l1, 1);
    l1 += __shfl_xor_sync(0xffffffffu, l1, 2);
    float inv0 = 1.f / l0, inv1 = 1.f / l1;

    size_t row0 = (size_t)(b * SEQ + q0 + wid * 16 + r);
    size_t row1 = row0 + 8;
#pragma unroll
    for (int j = 0; j < 8; j++) {
        int col = hq * HD + j * 8 + c2;
        *(uint32_t*)&g_ah[row0 * QPOS + col] = pack_h2(o[j][0] * inv0, o[j][1] * inv0);
        *(uint32_t*)&g_ah[row1 * QPOS + col] = pack_h2(o[j][2] * inv1, o[j][3] * inv1);
    }
}

// ---------------------------------------------------------------------------
// kernel_launch
// ---------------------------------------------------------------------------
extern "C" void kernel_launch(void* const* d_in, const int* in_sizes, int n_in,
                              void* d_out, int out_size)
{
    const float* x    = (const float*)d_in[0];
    const float* Wqkv = (const float*)d_in[1];
    const float* Wo   = (const float*)d_in[2];
    float* out        = (float*)d_out;

    __half *xh, *wqh, *woh, *ah;
    cudaGetSymbolAddress((void**)&xh,  g_x);
    cudaGetSymbolAddress((void**)&wqh, g_wq);
    cudaGetSymbolAddress((void**)&woh, g_wo);
    cudaGetSymbolAddress((void**)&ah,  g_ah);

    cudaFuncSetAttribute(gemm_f16_kernel<0>,
                         cudaFuncAttributeMaxDynamicSharedMemorySize, GEMM_SMEM);
    cudaFuncSetAttribute(gemm_f16_kernel<1>,
                         cudaFuncAttributeMaxDynamicSharedMemorySize, GEMM_SMEM);
    cudaFuncSetAttribute(attn_f16_kernel,
                         cudaFuncAttributeMaxDynamicSharedMemorySize, ATTN_SMEM);

    // 1) fused fp16 conversion (x + Wqkv + Wo) + rope table
    {
        to_half_all_kernel<<<(N4_ALL + 255) / 256, 256>>>(x, Wqkv, Wo);
    }
    {
        int n = SEQ * 32;
        rope_table_kernel<<<(n + 255) / 256, 256>>>();
    }

    // 2) QKV projection (fp16 single-pass, 3-stage pipeline) + fused epilogue
    {
        dim3 grid(OPS / 128, MTOT / 128);
        gemm_f16_kernel<1><<<grid, 128, GEMM_SMEM>>>(xh, wqh, nullptr, OPS, DMODEL);
    }

    // 3) Flash attention (fp16, base-2 softmax)
    {
        dim3 grid(SEQ / 64, NH, BATCH);
        attn_f16_kernel<<<grid, 128, ATTN_SMEM>>>();
    }

    // 4) O-projection (fp16 single-pass, 3-stage pipeline)
    {
        dim3 grid(DMODEL / 128, MTOT / 128);
        gemm_f16_kernel<0><<<grid, 128, GEMM_SMEM>>>(ah, woh, out, DMODEL, DMODEL);
    }
}

// round 16
// speedup vs baseline: 1.1171x; 1.1171x over previous
#include <cuda_runtime.h>
#include <cuda_fp16.h>
#include <math.h>
#include <stdint.h>

// Problem constants
#define BATCH   2
#define SEQ     2048
#define DMODEL  2048
#define NH      32
#define NKV     8
#define HD      64
#define QPOS    (NH * HD)            // 2048
#define KVPOS   (NKV * HD)           // 512
#define OPS     (QPOS + 2 * KVPOS)   // 3072
#define MTOT    (BATCH * SEQ)        // 4096
// q is pre-scaled by ATTN_SCALE * log2(e); softmax runs in base-2 domain
#define QSCALE  (0.125f * 1.4426950408889634f)

// ---------------------------------------------------------------------------
// Scratch (device globals) — fp16 operands everywhere, fp32 accumulate
// ---------------------------------------------------------------------------
__device__ __half g_x [MTOT * DMODEL];
__device__ __half g_wq[OPS * DMODEL];
__device__ __half g_wo[DMODEL * DMODEL];
// per-head-contiguous roped q/k and v: [b][h][seq][64]
__device__ __half g_qh[BATCH * NH  * SEQ * HD];
__device__ __half g_kh[BATCH * NKV * SEQ * HD];
__device__ __half g_vh[BATCH * NKV * SEQ * HD];
// attention output [row][2048] (O-proj A operand)
__device__ __half g_ah[MTOT * QPOS];
__device__ float2 g_rope[SEQ * 32];

// ---------------------------------------------------------------------------
// helpers
// ---------------------------------------------------------------------------
__device__ __forceinline__ uint32_t smem_to_u32(const void* p) {
    uint32_t a;
    asm("{ .reg .u64 t; cvta.to.shared.u64 t, %1; cvt.u32.u64 %0, t; }"
        : "=r"(a) : "l"(p));
    return a;
}

__device__ __forceinline__ void cp_async16(uint32_t smem_dst, const void* gmem_src) {
    asm volatile("cp.async.cg.shared.global [%0], [%1], 16;"
                 :: "r"(smem_dst), "l"(gmem_src) : "memory");
}
__device__ __forceinline__ void cp_commit() {
    asm volatile("cp.async.commit_group;" ::: "memory");
}
__device__ __forceinline__ void cp_wait0() {
    asm volatile("cp.async.wait_group 0;" ::: "memory");
}
__device__ __forceinline__ void cp_wait1() {
    asm volatile("cp.async.wait_group 1;" ::: "memory");
}

__device__ __forceinline__ void ldsm_x4(uint32_t& r0, uint32_t& r1,
                                        uint32_t& r2, uint32_t& r3, uint32_t addr) {
    asm volatile("ldmatrix.sync.aligned.m8n8.x4.shared.b16 {%0,%1,%2,%3}, [%4];"
                 : "=r"(r0), "=r"(r1), "=r"(r2), "=r"(r3) : "r"(addr));
}
__device__ __forceinline__ void ldsm_x4_trans(uint32_t& r0, uint32_t& r1,
                                              uint32_t& r2, uint32_t& r3, uint32_t addr) {
    asm volatile("ldmatrix.sync.aligned.m8n8.x4.trans.shared.b16 {%0,%1,%2,%3}, [%4];"
                 : "=r"(r0), "=r"(r1), "=r"(r2), "=r"(r3) : "r"(addr));
}

// fp16 mma m16n8k16, fp32 accumulate
__device__ __forceinline__ void mma_f16(float& d0, float& d1, float& d2, float& d3,
                                        uint32_t a0, uint32_t a1, uint32_t a2, uint32_t a3,
                                        uint32_t b0, uint32_t b1) {
    asm volatile(
        "mma.sync.aligned.m16n8k16.row.col.f32.f16.f16.f32 "
        "{%0,%1,%2,%3}, {%4,%5,%6,%7}, {%8,%9}, {%0,%1,%2,%3};"
        : "+f"(d0), "+f"(d1), "+f"(d2), "+f"(d3)
        : "r"(a0), "r"(a1), "r"(a2), "r"(a3), "r"(b0), "r"(b1));
}

__device__ __forceinline__ uint32_t pack_h2(float x, float y) {
    __half2 t = __floats2half2_rn(x, y);
    return *(uint32_t*)&t;
}

__device__ __forceinline__ float ex2f(float x) {
    float y;
    asm("ex2.approx.f32 %0, %1;" : "=f"(y) : "f"(x));
    return y;
}

// ---------------------------------------------------------------------------
// Fused conversion: x, Wqkv, Wo -> fp16 in one launch (segment select)
// ---------------------------------------------------------------------------
#define N4_X  ((MTOT * DMODEL) / 4)
#define N4_WQ ((OPS * DMODEL) / 4)
#define N4_WO ((DMODEL * DMODEL) / 4)
#define N4_ALL (N4_X + N4_WQ + N4_WO)

__global__ void to_half_all_kernel(const float* __restrict__ x,
                                   const float* __restrict__ wq,
                                   const float* __restrict__ wo)
{
    int i = blockIdx.x * blockDim.x + threadIdx.x;
    if (i >= N4_ALL) return;
    const float* src;
    __half* dst;
    int j = i;
    if (j < N4_X) {
        src = x;  dst = g_x;
    } else if ((j -= N4_X) < N4_WQ) {
        src = wq; dst = g_wq;
    } else {
        j -= N4_WQ;
        src = wo; dst = g_wo;
    }
    float4 v = ((const float4*)src)[j];
    uint32_t* dp = (uint32_t*)dst;
    dp[2 * j]     = pack_h2(v.x, v.y);
    dp[2 * j + 1] = pack_h2(v.z, v.w);
}

__global__ void rope_table_kernel()
{
    int idx = blockIdx.x * blockDim.x + threadIdx.x;
    if (idx >= SEQ * 32) return;
    int l = idx >> 5, i = idx & 31;
    float ang = (float)l * powf(10000.0f, -(float)(2 * i) / (float)HD);
    float s, c;
    sincosf(ang, &s, &c);
    g_rope[idx] = make_float2(c, s);
}

// ---------------------------------------------------------------------------
// Single-pass fp16 GEMM: C[M,N] = A[M,K] * B[N,K]^T, fp32 accumulate.
// CTA tile 128x128, K-chunk 32, THREE-stage cp.async pipeline (wait_group 1).
// 4 warps (2m x 2n), warp tile 64x64. 2 CTAs/SM (R14 config — reg cap 256).
// MODE 0: fp32 C (O-projection).
// MODE 1: QKV epilogue — RoPE, fp16-round, per-head scatter.
//         q heads additionally scaled by QSCALE (softmax base-2 + attn scale).
// ---------------------------------------------------------------------------
#define LDSE  40                         // halves per smem row (80 B, conflict-free)
#define LDSB  (LDSE * 2)
#define TILE_B (128 * LDSB)              // 10240 B per operand
#define STAGE_B (2 * TILE_B)             // 20480 B per stage
#define NSTAGE 3
#define GEMM_SMEM (NSTAGE * STAGE_B)     // 61440 B; x2 CTAs = 120 KB

template <int MODE>
__global__ void __launch_bounds__(128, 2)
gemm_f16_kernel(const __half* __restrict__ A, const __half* __restrict__ B,
                float* __restrict__ C, int N, int K)
{
    extern __shared__ char smem[];
    const uint32_t sb = smem_to_u32(smem);

    const int tid  = threadIdx.x;
    const int lane = tid & 31;
    const int wid  = tid >> 5;
    const int wm   = wid >> 1;           // 0..1
    const int wn   = wid & 1;            // 0..1
    const int bm   = blockIdx.y * 128;
    const int bn   = blockIdx.x * 128;

    const __half* Ag = A + (size_t)bm * K;
    const __half* Bg = B + (size_t)bn * K;

    const int r0 = tid >> 2;             // rows 0..31 (+32*i)
    const int c0 = tid & 3;

    float acc[4][8][4];
#pragma unroll
    for (int i = 0; i < 4; i++)
#pragma unroll
        for (int j = 0; j < 8; j++)
#pragma unroll
            for (int t = 0; t < 4; t++) acc[i][j][t] = 0.f;

    const int iters = K / 32;

    const uint32_t a_ld_off =
        (uint32_t)((wm * 64 + (lane & 15)) * LDSB + (lane >> 4) * 16);
    const uint32_t b_ld_off =
        (uint32_t)((wn * 64 + (lane & 7) + ((lane >> 4) << 3)) * LDSB
                   + ((lane >> 3) & 1) * 16);

    auto load_stage = [&](int stage, int k0) {
        uint32_t base = sb + stage * STAGE_B;
#pragma unroll
        for (int i = 0; i < 4; i++) {
            int row = r0 + i * 32;
            uint32_t sofs = (uint32_t)(row * LDSB + c0 * 16);
            size_t gofs   = (size_t)row * K + k0 + c0 * 8;
            cp_async16(base + sofs,          Ag + gofs);
            cp_async16(base + TILE_B + sofs, Bg + gofs);
        }
        cp_commit();
    };

    load_stage(0, 0);
    load_stage(1, 32);

    for (int it = 0; it < iters; ++it) {
        if (it + 1 < iters) cp_wait1(); else cp_wait0();
        __syncthreads();
        if (it + 2 < iters) load_stage((it + 2) % NSTAGE, (it + 2) * 32);

        const uint32_t base = sb + (it % NSTAGE) * STAGE_B;
        const uint32_t sA = base + a_ld_off;
        const uint32_t sB = base + TILE_B + b_ld_off;

#pragma unroll
        for (int ks = 0; ks < 2; ks++) {
            const uint32_t kofs = ks * 32;       // 16 halves = 32 B
            uint32_t af[4][4];
#pragma unroll
            for (int mt = 0; mt < 4; mt++)
                ldsm_x4(af[mt][0], af[mt][1], af[mt][2], af[mt][3],
                        sA + mt * 16 * LDSB + kofs);
#pragma unroll
            for (int np = 0; np < 4; np++) {
                uint32_t bf[4];
                ldsm_x4(bf[0], bf[1], bf[2], bf[3], sB + np * 16 * LDSB + kofs);
                const int j0 = 2 * np, j1 = 2 * np + 1;
#pragma unroll
                for (int mt = 0; mt < 4; mt++) {
                    mma_f16(acc[mt][j0][0], acc[mt][j0][1], acc[mt][j0][2], acc[mt][j0][3],
                            af[mt][0], af[mt][1], af[mt][2], af[mt][3], bf[0], bf[1]);
                    mma_f16(acc[mt][j1][0], acc[mt][j1][1], acc[mt][j1][2], acc[mt][j1][3],
                            af[mt][0], af[mt][1], af[mt][2], af[mt][3], bf[2], bf[3]);
                }
            }
        }
    }

    const int c2v = (lane & 3) * 2;

    if (MODE == 0) {
#pragma unroll
        for (int mt = 0; mt < 4; mt++) {
            int row = bm + wm * 64 + mt * 16 + (lane >> 2);
#pragma unroll
            for (int nt = 0; nt < 8; nt++) {
                int col = bn + wn * 64 + nt * 8 + c2v;
                *(float2*)&C[(size_t)row * N + col] =
                    make_float2(acc[mt][nt][0], acc[mt][nt][1]);
                *(float2*)&C[(size_t)(row + 8) * N + col] =
                    make_float2(acc[mt][nt][2], acc[mt][nt][3]);
            }
        }
    } else {
        // QKV epilogue: rope + fp16-round + per-head scatter (warp panel = 1 head)
        const int head = (bn + wn * 64) >> 6;   // 0..47
#pragma unroll
        for (int mt = 0; mt < 4; mt++) {
            int grow = bm + wm * 64 + mt * 16 + (lane >> 2);
            int b = grow >> 11;
            int l = grow & (SEQ - 1);
            __half* dh;
            bool rope;
            float sc = 1.f;
            if (head < NH) {
                dh = g_qh + ((size_t)(b * NH + head) * SEQ + l) * HD;
                rope = true;
                sc = QSCALE;                      // pre-scale q for base-2 softmax
            } else if (head < NH + NKV) {
                dh = g_kh + ((size_t)(b * NKV + (head - NH)) * SEQ + l) * HD;
                rope = true;
            } else {
                dh = g_vh + ((size_t)(b * NKV + (head - NH - NKV)) * SEQ + l) * HD;
                rope = false;
            }
#pragma unroll
            for (int nt = 0; nt < 4; nt++) {
                int i0 = nt * 8 + c2v;
                float x0 = acc[mt][nt][0],     x1 = acc[mt][nt][1];
                float y0 = acc[mt][nt + 4][0], y1 = acc[mt][nt + 4][1];
                float x2 = acc[mt][nt][2],     x3 = acc[mt][nt][3];
                float y2 = acc[mt][nt + 4][2], y3 = acc[mt][nt + 4][3];
                if (rope) {
                    float2 cs0 = g_rope[l * 32 + i0];
                    float2 cs1 = g_rope[l * 32 + i0 + 1];
                    float2 cs2 = g_rope[(l + 8) * 32 + i0];
                    float2 cs3 = g_rope[(l + 8) * 32 + i0 + 1];
                    float nx;
                    nx = x0 * cs0.x - y0 * cs0.y; y0 = y0 * cs0.x + x0 * cs0.y; x0 = nx;
                    nx = x1 * cs1.x - y1 * cs1.y; y1 = y1 * cs1.x + x1 * cs1.y; x1 = nx;
                    nx = x2 * cs2.x - y2 * cs2.y; y2 = y2 * cs2.x + x2 * cs2.y; x2 = nx;
                    nx = x3 * cs3.x - y3 * cs3.y; y3 = y3 * cs3.x + x3 * cs3.y; x3 = nx;
                }
                *(uint32_t*)(dh + i0)               = pack_h2(x0 * sc, x1 * sc);
                *(uint32_t*)(dh + i0 + 32)          = pack_h2(y0 * sc, y1 * sc);
                *(uint32_t*)(dh + 8 * HD + i0)      = pack_h2(x2 * sc, x3 * sc);
                *(uint32_t*)(dh + 8 * HD + i0 + 32) = pack_h2(y2 * sc, y3 * sc);
            }
        }
    }
}

// ---------------------------------------------------------------------------
// Flash attention, single-pass fp16 mma, base-2 softmax (q pre-scaled).
// CTA: 64 q-rows, 4 warps. KV tiles of 64 keys, double-buffered, 3 CTAs/SM.
// (R15 config — measured 137.7 us at 154 regs.)
// ---------------------------------------------------------------------------
#define A_LDSB  144                      // 72 halves per row
#define A_TILE  (64 * A_LDSB)            // 9216 B
#define A_STAGE (2 * A_TILE)             // K + V = 18432 B
#define ATTN_SMEM (2 * A_STAGE)          // 36864 B; x3 CTAs = 110 KB
#define AT_KH 0
#define AT_VH A_TILE

__global__ void __launch_bounds__(128, 3)
attn_f16_kernel()
{
    extern __shared__ char smem[];
    const uint32_t sb = smem_to_u32(smem);

    const int tid  = threadIdx.x;
    const int lane = tid & 31;
    const int wid  = tid >> 5;
    const int bx   = (int)gridDim.x - 1 - (int)blockIdx.x;   // heavy first
    const int q0   = bx * 64;
    const int hq   = blockIdx.y;
    const int b    = blockIdx.z;
    const int kvh  = hq >> 2;
    const int r    = lane >> 2;
    const int c2   = (lane & 3) * 2;

    const size_t qoff = ((size_t)(b * NH + hq) * SEQ + q0 + wid * 16 + r) * HD;
    const __half* qh0 = g_qh + qoff;
    const __half* qh1 = qh0 + 8 * HD;
    uint32_t qf[4][4];
#pragma unroll
    for (int ks = 0; ks < 4; ks++) {
        qf[ks][0] = *(const uint32_t*)(qh0 + ks * 16 + c2);
        qf[ks][1] = *(const uint32_t*)(qh1 + ks * 16 + c2);
        qf[ks][2] = *(const uint32_t*)(qh0 + ks * 16 + c2 + 8);
        qf[ks][3] = *(const uint32_t*)(qh1 + ks * 16 + c2 + 8);
    }

    const __half* kg = g_kh + (size_t)(b * NKV + kvh) * SEQ * HD;
    const __half* vg = g_vh + (size_t)(b * NKV + kvh) * SEQ * HD;

    auto load_stage = [&](int st, int kt) {
        uint32_t base = sb + st * A_STAGE;
#pragma unroll
        for (int i = 0; i < 4; i++) {
            int lin = tid + i * 128;
            int row = lin >> 3;
            int c   = lin & 7;
            uint32_t sofs = (uint32_t)(row * A_LDSB + c * 16);
            size_t gofs   = (size_t)(kt + row) * HD + c * 8;
            cp_async16(base + AT_KH + sofs, kg + gofs);
            cp_async16(base + AT_VH + sofs, vg + gofs);
        }
        cp_commit();
    };

    const int iters = bx + 1;
    load_stage(0, 0);

    float o[8][4];
#pragma unroll
    for (int j = 0; j < 8; j++)
#pragma unroll
        for (int t = 0; t < 4; t++) o[j][t] = 0.f;
    float m0 = -1e30f, m1 = -1e30f, l0 = 0.f, l1 = 0.f;

    const uint32_t kcore = (uint32_t)(((lane & 7) + ((lane >> 4) << 3)) * A_LDSB
                                      + ((lane >> 3) & 1) * 16);
    const uint32_t vcore = (uint32_t)((lane & 15) * A_LDSB + ((lane >> 4) << 4));

    for (int it = 0; it < iters; ++it) {
        const int kt = it * 64;
        cp_wait0();
        __syncthreads();
        if (it + 1 < iters) load_stage((it + 1) & 1, (it + 1) * 64);

        const uint32_t base = sb + (it & 1) * A_STAGE;

        // ---- S = Q K^T (q pre-scaled; scores already in log2 domain)
        float s[8][4];
#pragma unroll
        for (int j = 0; j < 8; j++)
#pragma unroll
            for (int t = 0; t < 4; t++) s[j][t] = 0.f;

#pragma unroll
        for (int kk = 0; kk < 4; kk++) {
#pragma unroll
            for (int np = 0; np < 4; np++) {
                uint32_t kb[4];
                ldsm_x4(kb[0], kb[1], kb[2], kb[3],
                        base + AT_KH + kcore + np * 16 * A_LDSB + kk * 32);
                int j0 = 2 * np, j1 = 2 * np + 1;
                mma_f16(s[j0][0], s[j0][1], s[j0][2], s[j0][3],
                        qf[kk][0], qf[kk][1], qf[kk][2], qf[kk][3], kb[0], kb[1]);
                mma_f16(s[j1][0], s[j1][1], s[j1][2], s[j1][3],
                        qf[kk][0], qf[kk][1], qf[kk][2], qf[kk][3], kb[2], kb[3]);
            }
        }

        if (kt == q0) {
            int row0 = q0 + wid * 16 + r;
#pragma unroll
            for (int j = 0; j < 8; j++) {
                int col = kt + j * 8 + c2;
                if (col > row0)     s[j][0] = -1e30f;
                if (col + 1 > row0) s[j][1] = -1e30f;
                if (col > row0 + 8)     s[j][2] = -1e30f;
                if (col + 1 > row0 + 8) s[j][3] = -1e30f;
            }
        }

        // ---- online softmax (base 2)
        float mx0 = -1e30f, mx1 = -1e30f;
#pragma unroll
        for (int j = 0; j < 8; j++) {
            mx0 = fmaxf(mx0, fmaxf(s[j][0], s[j][1]));
            mx1 = fmaxf(mx1, fmaxf(s[j][2], s[j][3]));
        }
        mx0 = fmaxf(mx0, __shfl_xor_sync(0xffffffffu, mx0, 1));
        mx0 = fmaxf(mx0, __shfl_xor_sync(0xffffffffu, mx0, 2));
        mx1 = fmaxf(mx1, __shfl_xor_sync(0xffffffffu, mx1, 1));
        mx1 = fmaxf(mx1, __shfl_xor_sync(0xffffffffu, mx1, 2));

        if (mx0 > m0) {
            float corr0 = ex2f(m0 - mx0);
            l0 *= corr0;
#pragma unroll
            for (int j = 0; j < 8; j++) { o[j][0] *= corr0; o[j][1] *= corr0; }
            m0 = mx0;
        }
        if (mx1 > m1) {
            float corr1 = ex2f(m1 - mx1);
            l1 *= corr1;
#pragma unroll
            for (int j = 0; j < 8; j++) { o[j][2] *= corr1; o[j][3] *= corr1; }
            m1 = mx1;
        }

#pragma unroll
        for (int j = 0; j < 8; j++) {
            float p0 = ex2f(s[j][0] - m0);
            float p1 = ex2f(s[j][1] - m0);
            float p2 = ex2f(s[j][2] - m1);
            float p3 = ex2f(s[j][3] - m1);
            l0 += p0 + p1; l1 += p2 + p3;
            s[j][0] = p0; s[j][1] = p1; s[j][2] = p2; s[j][3] = p3;
        }

        // ---- O += P V (fp16). P A-fragments from S registers (FA2 identity)
#pragma unroll
        for (int kk = 0; kk < 4; kk++) {
            uint32_t pa[4];
            pa[0] = pack_h2(s[2*kk][0],   s[2*kk][1]);
            pa[1] = pack_h2(s[2*kk][2],   s[2*kk][3]);
            pa[2] = pack_h2(s[2*kk+1][0], s[2*kk+1][1]);
            pa[3] = pack_h2(s[2*kk+1][2], s[2*kk+1][3]);
#pragma unroll
            for (int np = 0; np < 4; np++) {
                uint32_t vb[4];
                ldsm_x4_trans(vb[0], vb[1], vb[2], vb[3],
                              base + AT_VH + vcore + kk * 16 * A_LDSB + np * 32);
                int j0 = 2 * np, j1 = 2 * np + 1;
                mma_f16(o[j0][0], o[j0][1], o[j0][2], o[j0][3],
                        pa[0], pa[1], pa[2], pa[3], vb[0], vb[1]);
                mma_f16(o[j1][0], o[j1][1], o[j1][2], o[j1][3],
                        pa[0], pa[1], pa[2], pa[3], vb[2], vb[3]);
            }
        }
    }

    l0 += __shfl_xor_sync(0xffffffffu, l0, 1);
    l0 += __shfl_xor_sync(0xffffffffu, l0, 2);
    l1 += __shfl_xor_sync(0xffffffffu, l1, 1);
    l1 += __shfl_xor_sync(0xffffffffu, l1, 2);
    float inv0 = 1.f / l0, inv1 = 1.f / l1;

    size_t row0 = (size_t)(b * SEQ + q0 + wid * 16 + r);
    size_t row1 = row0 + 8;
#pragma unroll
    for (int j = 0; j < 8; j++) {
        int col = hq * HD + j * 8 + c2;
        *(uint32_t*)&g_ah[row0 * QPOS + col] = pack_h2(o[j][0] * inv0, o[j][1] * inv0);
        *(uint32_t*)&g_ah[row1 * QPOS + col] = pack_h2(o[j][2] * inv1, o[j][3] * inv1);
    }
}

// ---------------------------------------------------------------------------
// kernel_launch
// ---------------------------------------------------------------------------
extern "C" void kernel_launch(void* const* d_in, const int* in_sizes, int n_in,
                              void* d_out, int out_size)
{
    const float* x    = (const float*)d_in[0];
    const float* Wqkv = (const float*)d_in[1];
    const float* Wo   = (const float*)d_in[2];
    float* out        = (float*)d_out;

    __half *xh, *wqh, *woh, *ah;
    cudaGetSymbolAddress((void**)&xh,  g_x);
    cudaGetSymbolAddress((void**)&wqh, g_wq);
    cudaGetSymbolAddress((void**)&woh, g_wo);
    cudaGetSymbolAddress((void**)&ah,  g_ah);

    cudaFuncSetAttribute(gemm_f16_kernel<0>,
                         cudaFuncAttributeMaxDynamicSharedMemorySize, GEMM_SMEM);
    cudaFuncSetAttribute(gemm_f16_kernel<1>,
                         cudaFuncAttributeMaxDynamicSharedMemorySize, GEMM_SMEM);
    cudaFuncSetAttribute(attn_f16_kernel,
                         cudaFuncAttributeMaxDynamicSharedMemorySize, ATTN_SMEM);

    // 1) fused fp16 conversion (x + Wqkv + Wo) + rope table
    {
        to_half_all_kernel<<<(N4_ALL + 255) / 256, 256>>>(x, Wqkv, Wo);
    }
    {
        int n = SEQ * 32;
        rope_table_kernel<<<(n + 255) / 256, 256>>>();
    }

    // 2) QKV projection (fp16 single-pass, 3-stage pipeline, 2 CTAs/SM)
    {
        dim3 grid(OPS / 128, MTOT / 128);
        gemm_f16_kernel<1><<<grid, 128, GEMM_SMEM>>>(xh, wqh, nullptr, OPS, DMODEL);
    }

    // 3) Flash attention (fp16, base-2 softmax, 3 CTAs/SM)
    {
        dim3 grid(SEQ / 64, NH, BATCH);
        attn_f16_kernel<<<grid, 128, ATTN_SMEM>>>();
    }

    // 4) O-projection (fp16 single-pass, 3-stage pipeline, 2 CTAs/SM)
    {
        dim3 grid(DMODEL / 128, MTOT / 128);
        gemm_f16_kernel<0><<<grid, 128, GEMM_SMEM>>>(ah, woh, out, DMODEL, DMODEL);
    }
}